// round 6
// baseline (speedup 1.0000x reference)
#include <cuda_runtime.h>

// DecoderRNN on GB300 — fully fused per-row LSTM recurrence.
// R4 change: RB 32 -> 16 (smem 192KB -> 96KB) => 2 CTAs/SM, 4 warps/SMSP,
// halved acc register pressure, unroll 4 in the hot k-loop for more MLP.
//
//  * rows independent -> 16 rows/block, 4096 blocks
//  * x@W_ih^T decomposed: z-part computed once per branch; bid/aid/action-emb
//    parts precomputed as tables (Cbase[4][1024], Gp[16][1024])
//  * hot loop = h@W_hh^T with k-major transposed weights + packed fma.rn.f32x2
//  * thread t owns hidden unit t (gate rows t, t+256, t+512, t+768)

typedef unsigned long long ull;

#define BATCH  65536
#define RB     16       // rows per block
#define RPAIR  8        // RB/2
#define NTH    256
#define NTT    4        // NT
#define NMM    11       // NM
#define SSS    4        // S
#define NEGBIG -1000000000.0f

__device__ float g_WhhT[256*1024];   // [k][gate]
__device__ float g_WzT [256*1024];   // [k][gate] (z columns of W_ih)
__device__ float g_Cbase[4*1024];    // [branch*2+aid][gate] = bid+aid+bias
__device__ float g_Gp  [16*1024];    // [prev][gate] action-emb contribution
__device__ float g_ent [2];          // raw entropy sums (t, m)

__device__ __forceinline__ ull dupf(float x){ ull r; asm("mov.b64 %0, {%1, %1};" : "=l"(r) : "f"(x)); return r; }
__device__ __forceinline__ ull packf(float x, float y){ ull r; asm("mov.b64 %0, {%1, %2};" : "=l"(r) : "f"(x), "f"(y)); return r; }
__device__ __forceinline__ float2 unpackf(ull v){ float2 r; asm("mov.b64 {%0, %1}, %2;" : "=f"(r.x), "=f"(r.y) : "l"(v)); return r; }
__device__ __forceinline__ void fma2(ull &d, ull a, ull b){ asm("fma.rn.f32x2 %0, %1, %2, %0;" : "+l"(d) : "l"(a), "l"(b)); }

__device__ __forceinline__ float sigf(float x){ return 1.0f/(1.0f + __expf(-x)); }
__device__ __forceinline__ float tanh_f(float x){ return 1.0f - 2.0f/(__expf(2.0f*x)+1.0f); }

// acc[gi][rp] (+)= sum_k WT[k][gi*256+t] * hb[rp][k]   (packed row pairs)
__device__ __forceinline__ void gemm256(const float* __restrict__ WT,
                                        const ull* __restrict__ hb,
                                        int t, ull (&acc)[4][RPAIR])
{
  #pragma unroll 4
  for (int k=0;k<256;k++){
    const float* wr = WT + (k<<10) + t;
    ull w0 = dupf(wr[0]);
    ull w1 = dupf(wr[256]);
    ull w2 = dupf(wr[512]);
    ull w3 = dupf(wr[768]);
    const ull* hk = hb + k;
    #pragma unroll
    for (int rp=0;rp<RPAIR;rp++){
      ull hp = hk[rp<<8];
      fma2(acc[0][rp], w0, hp);
      fma2(acc[1][rp], w1, hp);
      fma2(acc[2][rp], w2, hp);
      fma2(acc[3][rp], w3, hp);
    }
  }
}

// ---------------------------------------------------------------- prep ----
__global__ void prep_kernel(const float* __restrict__ Wih, const float* __restrict__ Whh,
                            const float* __restrict__ bih, const float* __restrict__ bhh,
                            const float* __restrict__ aemb, const float* __restrict__ bemb,
                            const float* __restrict__ idemb)
{
  int g = blockIdx.x*blockDim.x + threadIdx.x;
  if (g==0){ g_ent[0]=0.f; g_ent[1]=0.f; }
  if (g>=1024) return;
  for (int k=0;k<256;k++){
    g_WhhT[k*1024+g] = Whh[g*256+k];
    g_WzT [k*1024+g] = Wih[g*448+k];
  }
  float bsum = bih[g]+bhh[g];
  float sb[2], sa[2];
  for (int br=0;br<2;br++){ float s=0.f; for(int e=0;e<64;e++) s += Wih[g*448+256+e]*bemb[br*64+e]; sb[br]=s; }
  for (int a=0;a<2;a++){ float s=0.f; for(int e=0;e<64;e++) s += Wih[g*448+320+e]*idemb[a*64+e]; sa[a]=s; }
  for (int br=0;br<2;br++)
    for (int a=0;a<2;a++)
      g_Cbase[(br*2+a)*1024+g] = bsum + sb[br] + sa[a];
  for (int p=0;p<16;p++){
    float s=0.f;
    for (int e=0;e<64;e++) s += Wih[g*448+384+e]*aemb[p*64+e];
    g_Gp[p*1024+g] = s;
  }
}

// ---------------------------------------------------------------- main ----
__global__ void __launch_bounds__(NTH,2) decoder_kernel(
  const float* __restrict__ z1, const float* __restrict__ z2,
  const int* __restrict__ t_act, const int* __restrict__ m_act,
  const float* __restrict__ Wt, const float* __restrict__ bt,
  const float* __restrict__ Wm, const float* __restrict__ bm,
  float* __restrict__ out)
{
  extern __shared__ ull smem_u[];
  ull* sh_h  = smem_u;                  // [RPAIR][256] packed h row-pairs
  ull* sh_z  = smem_u + RPAIR*256;      // [RPAIR][256] packed z row-pairs
  ull* sh_wz = smem_u + 2*RPAIR*256;    // [4][RPAIR][256] per-thread Wz
  __shared__ int   s_pidx[RB];
  __shared__ int   s_mask[RB];
  __shared__ float s_lp[RB];
  __shared__ float s_red[16];

  const int t    = threadIdx.x;
  const int wid  = t>>5, lane = t&31;
  const int r0   = blockIdx.x*RB;

  float c[RB];
  #pragma unroll
  for (int r=0;r<RB;r++) c[r]=0.f;
  for (int i=t;i<RPAIR*256;i+=NTH) sh_h[i]=0ull;
  if (t<RB){ s_pidx[t]=15; s_mask[t]=(1<<NTT)-1; s_lp[t]=0.f; }
  float eT=0.f, eM=0.f;

  for (int branch=0; branch<2; branch++){
    __syncthreads();   // protect s_mask / sh_z from previous phase
    const float* z = branch ? z2 : z1;
    for (int i=t;i<RB*256;i+=NTH){
      int rr=i>>8, k=i&255;
      ((float*)sh_z)[((rr>>1)<<9)+(k<<1)+(rr&1)] = z[(size_t)(r0+rr)*256+k];
    }
    if (t<RB) s_mask[t]=(1<<NTT)-1;
    __syncthreads();

    { // Wz = z @ W_ih[:, :256]^T  (per branch)
      ull acc[4][RPAIR];
      #pragma unroll
      for (int gi=0;gi<4;gi++)
        #pragma unroll
        for (int rp=0;rp<RPAIR;rp++) acc[gi][rp]=0ull;
      gemm256(g_WzT, sh_z, t, acc);
      #pragma unroll
      for (int gi=0;gi<4;gi++)
        #pragma unroll
        for (int rp=0;rp<RPAIR;rp++) sh_wz[((gi*RPAIR+rp)<<8)+t]=acc[gi][rp];
    }

    for (int sub=0; sub<2*SSS; sub++){
      int step = sub>>1;
      int isM  = sub&1;
      __syncthreads();   // wz/pidx/h ready

      ull acc[4][RPAIR];
      { // gate init: Wz + Cbase + Gp[pidx]
        const float* Cb = g_Cbase + (branch*2+isM)*1024 + t;
        #pragma unroll
        for (int gi=0;gi<4;gi++){
          float cb = Cb[gi<<8];
          #pragma unroll
          for (int rp=0;rp<RPAIR;rp++){
            float2 wzv = unpackf(sh_wz[((gi*RPAIR+rp)<<8)+t]);
            int p0 = s_pidx[2*rp], p1 = s_pidx[2*rp+1];
            float gx = g_Gp[p0*1024 + (gi<<8) + t];
            float gy = g_Gp[p1*1024 + (gi<<8) + t];
            acc[gi][rp] = packf(wzv.x+cb+gx, wzv.y+cb+gy);
          }
        }
      }
      gemm256(g_WhhT, sh_h, t, acc);
      __syncthreads();   // all reads of old h done

      // LSTM elementwise: thread t = hidden unit t
      #pragma unroll
      for (int rp=0;rp<RPAIR;rp++){
        float2 gi_ = unpackf(acc[0][rp]);
        float2 gf_ = unpackf(acc[1][rp]);
        float2 gg_ = unpackf(acc[2][rp]);
        float2 go_ = unpackf(acc[3][rp]);
        int ra=2*rp, rb2=ra+1;
        c[ra]  = sigf(gf_.x)*c[ra]  + sigf(gi_.x)*tanh_f(gg_.x);
        c[rb2] = sigf(gf_.y)*c[rb2] + sigf(gi_.y)*tanh_f(gg_.y);
        float hx = sigf(go_.x)*tanh_f(c[ra]);
        float hy = sigf(go_.y)*tanh_f(c[rb2]);
        sh_h[(rp<<8)+t] = packf(hx,hy);
      }
      __syncthreads();   // h ready for heads

      // heads: warp w handles rows 2w, 2w+1
      const float* hb = (const float*)sh_h;
      #pragma unroll
      for (int rr=0;rr<2;rr++){
        int r   = (wid<<1)+rr;
        int off = ((r>>1)<<9) + (r&1);
        if (!isM){
          float a0=0.f,a1=0.f,a2=0.f,a3=0.f;
          #pragma unroll
          for (int kk=0;kk<8;kk++){
            int k = lane + (kk<<5);
            float hv = hb[off + (k<<1)];
            a0 += Wt[      k]*hv;
            a1 += Wt[256 + k]*hv;
            a2 += Wt[512 + k]*hv;
            a3 += Wt[768 + k]*hv;
          }
          #pragma unroll
          for (int o=16;o;o>>=1){
            a0+=__shfl_xor_sync(0xffffffffu,a0,o);
            a1+=__shfl_xor_sync(0xffffffffu,a1,o);
            a2+=__shfl_xor_sync(0xffffffffu,a2,o);
            a3+=__shfl_xor_sync(0xffffffffu,a3,o);
          }
          int mk = s_mask[r];
          float l0 = (mk&1)? a0+bt[0] : NEGBIG;
          float l1 = (mk&2)? a1+bt[1] : NEGBIG;
          float l2 = (mk&4)? a2+bt[2] : NEGBIG;
          float l3 = (mk&8)? a3+bt[3] : NEGBIG;
          float mx = fmaxf(fmaxf(l0,l1),fmaxf(l2,l3));
          float e0=__expf(l0-mx), e1=__expf(l1-mx), e2=__expf(l2-mx), e3=__expf(l3-mx);
          float se = e0+e1+e2+e3;
          float sl = e0*l0+e1*l1+e2*l2+e3*l3;
          float lse = mx + __logf(se);
          int ta = t_act[(size_t)(r0+r)*8 + branch*4 + step];
          float lsel = (ta==0)? l0 : (ta==1)? l1 : (ta==2)? l2 : l3;
          float H = lse - sl/se;
          if (lane==0){
            s_lp[r]  += lsel - lse;
            s_mask[r] = mk & ~(1<<ta);
            s_pidx[r] = ta;            // LSTM#2 uses action_emb[ta]
            eT += H;
          }
        } else {
          float a[NMM];
          #pragma unroll
          for (int j=0;j<NMM;j++) a[j]=0.f;
          #pragma unroll
          for (int kk=0;kk<8;kk++){
            int k = lane + (kk<<5);
            float hv = hb[off + (k<<1)];
            #pragma unroll
            for (int j=0;j<NMM;j++) a[j] += Wm[j*256+k]*hv;
          }
          #pragma unroll
          for (int j=0;j<NMM;j++){
            #pragma unroll
            for (int o=16;o;o>>=1) a[j]+=__shfl_xor_sync(0xffffffffu,a[j],o);
          }
          float mx = -1e30f;
          #pragma unroll
          for (int j=0;j<NMM;j++){ a[j]+=bm[j]; mx = fmaxf(mx,a[j]); }
          float se=0.f, sl=0.f;
          #pragma unroll
          for (int j=0;j<NMM;j++){ float e=__expf(a[j]-mx); se+=e; sl+=e*a[j]; }
          float lse = mx + __logf(se);
          int ma = m_act[(size_t)(r0+r)*8 + branch*4 + step];
          float lsel = a[0];
          #pragma unroll
          for (int j=1;j<NMM;j++) lsel = (j==ma)? a[j] : lsel;
          float H = lse - sl/se;
          if (lane==0){
            s_lp[r]  += lsel - lse;
            s_pidx[r] = ma;            // next step's prev
            eM += H;
          }
        }
      }
    }
  }

  __syncthreads();
  if (t<RB) out[r0+t] = s_lp[t];
  if (lane==0){ s_red[wid]=eT; s_red[8+wid]=eM; }
  __syncthreads();
  if (t==0){
    float sT=0.f,sM=0.f;
    for (int w=0;w<8;w++){ sT+=s_red[w]; sM+=s_red[8+w]; }
    atomicAdd(&g_ent[0],sT);
    atomicAdd(&g_ent[1],sM);
  }
}

// ----------------------------------------------------------- epilogue ----
__global__ void finalize_kernel(float* __restrict__ out, int off){
  if (threadIdx.x==0 && blockIdx.x==0){
    const float sc = 1.0f/(65536.0f*8.0f);  // mean over B, then /(2S)
    out[off]   = g_ent[0]*sc;
    out[off+1] = g_ent[1]*sc;
  }
}

__global__ void cvt_kernel(const int* __restrict__ ti, const int* __restrict__ mi,
                           float* __restrict__ out){
  int i = blockIdx.x*blockDim.x + threadIdx.x;
  if (i < 65536*8){
    out[65536 + i]           = (float)ti[i];
    out[65536 + 65536*8 + i] = (float)mi[i];
  }
}

// ---------------------------------------------------------------- host ----
extern "C" void kernel_launch(void* const* d_in, const int* in_sizes, int n_in,
                              void* d_out, int out_size)
{
  (void)in_sizes; (void)n_in;
  const float* z1    = (const float*)d_in[0];
  const float* z2    = (const float*)d_in[1];
  const int*   t_act = (const int*)  d_in[2];
  const int*   m_act = (const int*)  d_in[3];
  const float* aemb  = (const float*)d_in[4];
  const float* bemb  = (const float*)d_in[5];
  const float* idemb = (const float*)d_in[6];
  const float* Wih   = (const float*)d_in[7];
  const float* Whh   = (const float*)d_in[8];
  const float* bih   = (const float*)d_in[9];
  const float* bhh   = (const float*)d_in[10];
  const float* Wt    = (const float*)d_in[11];
  const float* bt    = (const float*)d_in[12];
  const float* Wm    = (const float*)d_in[13];
  const float* bm    = (const float*)d_in[14];
  float* out = (float*)d_out;

  const int SMEM_BYTES = (2*RPAIR*256 + 4*RPAIR*256) * (int)sizeof(ull); // 98304
  cudaFuncSetAttribute(decoder_kernel, cudaFuncAttributeMaxDynamicSharedMemorySize, SMEM_BYTES);

  prep_kernel<<<4,256>>>(Wih,Whh,bih,bhh,aemb,bemb,idemb);
  decoder_kernel<<<BATCH/RB, NTH, SMEM_BYTES>>>(z1,z2,t_act,m_act,Wt,bt,Wm,bm,out);

  const int NACT = 65536*8;  // elements in t_actions (= m_actions)
  if (out_size >= 65536 + 2*NACT + 2){
    // tree-flatten layout: [log_p | t_actions | m_actions | t_ent | m_ent]
    cvt_kernel<<<(NACT+255)/256,256>>>(t_act, m_act, out);
    finalize_kernel<<<1,32>>>(out, 65536 + 2*NACT);
  } else if (out_size >= 65536 + 2){
    finalize_kernel<<<1,32>>>(out, 65536);
  }
  // else: log_p-only layout; main kernel already wrote out[0..B)
}

// round 7
// speedup vs baseline: 1.1552x; 1.1552x over previous
#include <cuda_runtime.h>

// DecoderRNN on GB300 — fully fused per-row LSTM recurrence.
// R6 change: kernel was LSU-dispatch-bound (12 mem instrs per 32 FFMA2 per
// k-iter = ~512 LSU cyc/SM-k vs 256 FMA cyc). Fix the instruction mix:
//   * weights interleaved as W4[k][t][4] -> one LDG.128 per thread per k
//   * h stored k-major (stride 10 ull, padded) -> four LDS.128 broadcasts per k
// New LSU budget ~192 cyc/SM-k < 256 FMA cyc -> FMA-bound.

typedef unsigned long long ull;

#define BATCH  65536
#define RB     16       // rows per block
#define RPAIR  8        // RB/2
#define HSTR   10       // padded k-major stride (ull) for sh_h / sh_z
#define NTH    256
#define NTT    4        // NT
#define NMM    11       // NM
#define SSS    4        // S
#define NEGBIG -1000000000.0f

__device__ float4 g_W4  [256*256];   // [k][t] -> {w_i,w_f,w_g,w_o} of W_hh
__device__ float4 g_W4z [256*256];   // same for z-columns of W_ih
__device__ float  g_Cbase[4*1024];   // [branch*2+aid][gate] = bid+aid+bias
__device__ float  g_Gp  [16*1024];   // [prev][gate] action-emb contribution
__device__ float  g_ent [2];         // raw entropy sums (t, m)

__device__ __forceinline__ ull dupf(float x){ ull r; asm("mov.b64 %0, {%1, %1};" : "=l"(r) : "f"(x)); return r; }
__device__ __forceinline__ ull packf(float x, float y){ ull r; asm("mov.b64 %0, {%1, %2};" : "=l"(r) : "f"(x), "f"(y)); return r; }
__device__ __forceinline__ float2 unpackf(ull v){ float2 r; asm("mov.b64 {%0, %1}, %2;" : "=f"(r.x), "=f"(r.y) : "l"(v)); return r; }
__device__ __forceinline__ void fma2(ull &d, ull a, ull b){ asm("fma.rn.f32x2 %0, %1, %2, %0;" : "+l"(d) : "l"(a), "l"(b)); }

__device__ __forceinline__ float sigf(float x){ return 1.0f/(1.0f + __expf(-x)); }
__device__ __forceinline__ float tanh_f(float x){ return 1.0f - 2.0f/(__expf(2.0f*x)+1.0f); }

// acc[gi][rp] (+)= sum_k W4[k][t][gi] * hb[k][rp]   (packed row pairs, k-major h)
__device__ __forceinline__ void gemm256(const float4* __restrict__ W4,
                                        const ull* __restrict__ hb,
                                        int t, ull (&acc)[4][RPAIR])
{
  #pragma unroll 4
  for (int k=0;k<256;k++){
    float4 wv = W4[(k<<8) + t];               // LDG.128
    ull w0 = dupf(wv.x);
    ull w1 = dupf(wv.y);
    ull w2 = dupf(wv.z);
    ull w3 = dupf(wv.w);
    const ull* hk = hb + k*HSTR;
    ulonglong2 ha = *(const ulonglong2*)(hk+0);   // LDS.128 (broadcast)
    ulonglong2 hb2= *(const ulonglong2*)(hk+2);
    ulonglong2 hc = *(const ulonglong2*)(hk+4);
    ulonglong2 hd = *(const ulonglong2*)(hk+6);
    ull hp[RPAIR] = {ha.x,ha.y,hb2.x,hb2.y,hc.x,hc.y,hd.x,hd.y};
    #pragma unroll
    for (int rp=0;rp<RPAIR;rp++){
      fma2(acc[0][rp], w0, hp[rp]);
      fma2(acc[1][rp], w1, hp[rp]);
      fma2(acc[2][rp], w2, hp[rp]);
      fma2(acc[3][rp], w3, hp[rp]);
    }
  }
}

// ---------------------------------------------------------------- prep ----
__global__ void prep_w4_kernel(const float* __restrict__ Wih, const float* __restrict__ Whh)
{
  int idx = blockIdx.x*blockDim.x + threadIdx.x;   // 65536 = 256k x 256t
  if (idx >= 256*256) return;
  int k = idx>>8, t = idx&255;
  float4 w;
  w.x = Whh[( 0 +t)*256+k];
  w.y = Whh[(256+t)*256+k];
  w.z = Whh[(512+t)*256+k];
  w.w = Whh[(768+t)*256+k];
  g_W4[idx] = w;
  float4 wz;
  wz.x = Wih[( 0 +t)*448+k];
  wz.y = Wih[(256+t)*448+k];
  wz.z = Wih[(512+t)*448+k];
  wz.w = Wih[(768+t)*448+k];
  g_W4z[idx] = wz;
}

__global__ void prep_kernel(const float* __restrict__ Wih,
                            const float* __restrict__ bih, const float* __restrict__ bhh,
                            const float* __restrict__ aemb, const float* __restrict__ bemb,
                            const float* __restrict__ idemb)
{
  int g = blockIdx.x*blockDim.x + threadIdx.x;
  if (g==0){ g_ent[0]=0.f; g_ent[1]=0.f; }
  if (g>=1024) return;
  float bsum = bih[g]+bhh[g];
  float sb[2], sa[2];
  for (int br=0;br<2;br++){ float s=0.f; for(int e=0;e<64;e++) s += Wih[g*448+256+e]*bemb[br*64+e]; sb[br]=s; }
  for (int a=0;a<2;a++){ float s=0.f; for(int e=0;e<64;e++) s += Wih[g*448+320+e]*idemb[a*64+e]; sa[a]=s; }
  for (int br=0;br<2;br++)
    for (int a=0;a<2;a++)
      g_Cbase[(br*2+a)*1024+g] = bsum + sb[br] + sa[a];
  for (int p=0;p<16;p++){
    float s=0.f;
    for (int e=0;e<64;e++) s += Wih[g*448+384+e]*aemb[p*64+e];
    g_Gp[p*1024+g] = s;
  }
}

// ---------------------------------------------------------------- main ----
__global__ void __launch_bounds__(NTH,2) decoder_kernel(
  const float* __restrict__ z1, const float* __restrict__ z2,
  const int* __restrict__ t_act, const int* __restrict__ m_act,
  const float* __restrict__ Wt, const float* __restrict__ bt,
  const float* __restrict__ Wm, const float* __restrict__ bm,
  float* __restrict__ out)
{
  extern __shared__ ull smem_u[];
  ull* sh_h  = smem_u;                    // [256][HSTR] k-major packed h pairs
  ull* sh_z  = smem_u + 256*HSTR;         // [256][HSTR] k-major packed z pairs
  ull* sh_wz = smem_u + 2*256*HSTR;       // [4*RPAIR][256] per-thread Wz
  __shared__ int   s_pidx[RB];
  __shared__ int   s_mask[RB];
  __shared__ float s_lp[RB];
  __shared__ float s_red[16];

  const int t    = threadIdx.x;
  const int wid  = t>>5, lane = t&31;
  const int r0   = blockIdx.x*RB;

  float c[RB];
  #pragma unroll
  for (int r=0;r<RB;r++) c[r]=0.f;
  for (int i=t;i<256*HSTR;i+=NTH) sh_h[i]=0ull;
  if (t<RB){ s_pidx[t]=15; s_mask[t]=(1<<NTT)-1; s_lp[t]=0.f; }
  float eT=0.f, eM=0.f;

  for (int branch=0; branch<2; branch++){
    __syncthreads();   // protect s_mask / sh_z from previous phase
    const float* z = branch ? z2 : z1;
    for (int i=t;i<RB*256;i+=NTH){
      int rr=i>>8, k=i&255;
      ((float*)sh_z)[k*2*HSTR + rr] = z[(size_t)(r0+rr)*256+k];
    }
    if (t<RB) s_mask[t]=(1<<NTT)-1;
    __syncthreads();

    { // Wz = z @ W_ih[:, :256]^T  (per branch)
      ull acc[4][RPAIR];
      #pragma unroll
      for (int gi=0;gi<4;gi++)
        #pragma unroll
        for (int rp=0;rp<RPAIR;rp++) acc[gi][rp]=0ull;
      gemm256(g_W4z, sh_z, t, acc);
      #pragma unroll
      for (int gi=0;gi<4;gi++)
        #pragma unroll
        for (int rp=0;rp<RPAIR;rp++) sh_wz[((gi*RPAIR+rp)<<8)+t]=acc[gi][rp];
    }

    for (int sub=0; sub<2*SSS; sub++){
      int step = sub>>1;
      int isM  = sub&1;
      __syncthreads();   // wz/pidx/h ready

      ull acc[4][RPAIR];
      { // gate init: Wz + Cbase + Gp[pidx]
        const float* Cb = g_Cbase + (branch*2+isM)*1024 + t;
        #pragma unroll
        for (int gi=0;gi<4;gi++){
          float cb = Cb[gi<<8];
          #pragma unroll
          for (int rp=0;rp<RPAIR;rp++){
            float2 wzv = unpackf(sh_wz[((gi*RPAIR+rp)<<8)+t]);
            int p0 = s_pidx[2*rp], p1 = s_pidx[2*rp+1];
            float gx = g_Gp[p0*1024 + (gi<<8) + t];
            float gy = g_Gp[p1*1024 + (gi<<8) + t];
            acc[gi][rp] = packf(wzv.x+cb+gx, wzv.y+cb+gy);
          }
        }
      }
      gemm256(g_W4, sh_h, t, acc);
      __syncthreads();   // all reads of old h done

      // LSTM elementwise: thread t = hidden unit t; h stored k-major at k=t
      #pragma unroll
      for (int rp=0;rp<RPAIR;rp++){
        float2 gi_ = unpackf(acc[0][rp]);
        float2 gf_ = unpackf(acc[1][rp]);
        float2 gg_ = unpackf(acc[2][rp]);
        float2 go_ = unpackf(acc[3][rp]);
        int ra=2*rp, rb2=ra+1;
        c[ra]  = sigf(gf_.x)*c[ra]  + sigf(gi_.x)*tanh_f(gg_.x);
        c[rb2] = sigf(gf_.y)*c[rb2] + sigf(gi_.y)*tanh_f(gg_.y);
        float hx = sigf(go_.x)*tanh_f(c[ra]);
        float hy = sigf(go_.y)*tanh_f(c[rb2]);
        sh_h[t*HSTR + rp] = packf(hx,hy);
      }
      __syncthreads();   // h ready for heads

      // heads: warp w handles rows 2w, 2w+1; h[row r, unit k] = hbf[k*2*HSTR + r]
      const float* hbf = (const float*)sh_h;
      #pragma unroll
      for (int rr=0;rr<2;rr++){
        int r = (wid<<1)+rr;
        if (!isM){
          float a0=0.f,a1=0.f,a2=0.f,a3=0.f;
          #pragma unroll
          for (int kk=0;kk<8;kk++){
            int k = lane + (kk<<5);
            float hv = hbf[k*2*HSTR + r];
            a0 += Wt[      k]*hv;
            a1 += Wt[256 + k]*hv;
            a2 += Wt[512 + k]*hv;
            a3 += Wt[768 + k]*hv;
          }
          #pragma unroll
          for (int o=16;o;o>>=1){
            a0+=__shfl_xor_sync(0xffffffffu,a0,o);
            a1+=__shfl_xor_sync(0xffffffffu,a1,o);
            a2+=__shfl_xor_sync(0xffffffffu,a2,o);
            a3+=__shfl_xor_sync(0xffffffffu,a3,o);
          }
          int mk = s_mask[r];
          float l0 = (mk&1)? a0+bt[0] : NEGBIG;
          float l1 = (mk&2)? a1+bt[1] : NEGBIG;
          float l2 = (mk&4)? a2+bt[2] : NEGBIG;
          float l3 = (mk&8)? a3+bt[3] : NEGBIG;
          float mx = fmaxf(fmaxf(l0,l1),fmaxf(l2,l3));
          float e0=__expf(l0-mx), e1=__expf(l1-mx), e2=__expf(l2-mx), e3=__expf(l3-mx);
          float se = e0+e1+e2+e3;
          float sl = e0*l0+e1*l1+e2*l2+e3*l3;
          float lse = mx + __logf(se);
          int ta = t_act[(size_t)(r0+r)*8 + branch*4 + step];
          float lsel = (ta==0)? l0 : (ta==1)? l1 : (ta==2)? l2 : l3;
          float H = lse - sl/se;
          if (lane==0){
            s_lp[r]  += lsel - lse;
            s_mask[r] = mk & ~(1<<ta);
            s_pidx[r] = ta;            // LSTM#2 uses action_emb[ta]
            eT += H;
          }
        } else {
          float a[NMM];
          #pragma unroll
          for (int j=0;j<NMM;j++) a[j]=0.f;
          #pragma unroll
          for (int kk=0;kk<8;kk++){
            int k = lane + (kk<<5);
            float hv = hbf[k*2*HSTR + r];
            #pragma unroll
            for (int j=0;j<NMM;j++) a[j] += Wm[j*256+k]*hv;
          }
          #pragma unroll
          for (int j=0;j<NMM;j++){
            #pragma unroll
            for (int o=16;o;o>>=1) a[j]+=__shfl_xor_sync(0xffffffffu,a[j],o);
          }
          float mx = -1e30f;
          #pragma unroll
          for (int j=0;j<NMM;j++){ a[j]+=bm[j]; mx = fmaxf(mx,a[j]); }
          float se=0.f, sl=0.f;
          #pragma unroll
          for (int j=0;j<NMM;j++){ float e=__expf(a[j]-mx); se+=e; sl+=e*a[j]; }
          float lse = mx + __logf(se);
          int ma = m_act[(size_t)(r0+r)*8 + branch*4 + step];
          float lsel = a[0];
          #pragma unroll
          for (int j=1;j<NMM;j++) lsel = (j==ma)? a[j] : lsel;
          float H = lse - sl/se;
          if (lane==0){
            s_lp[r]  += lsel - lse;
            s_pidx[r] = ma;            // next step's prev
            eM += H;
          }
        }
      }
    }
  }

  __syncthreads();
  if (t<RB) out[r0+t] = s_lp[t];
  if (lane==0){ s_red[wid]=eT; s_red[8+wid]=eM; }
  __syncthreads();
  if (t==0){
    float sT=0.f,sM=0.f;
    for (int w=0;w<8;w++){ sT+=s_red[w]; sM+=s_red[8+w]; }
    atomicAdd(&g_ent[0],sT);
    atomicAdd(&g_ent[1],sM);
  }
}

// ----------------------------------------------------------- epilogue ----
__global__ void finalize_kernel(float* __restrict__ out, int off){
  if (threadIdx.x==0 && blockIdx.x==0){
    const float sc = 1.0f/(65536.0f*8.0f);  // mean over B, then /(2S)
    out[off]   = g_ent[0]*sc;
    out[off+1] = g_ent[1]*sc;
  }
}

__global__ void cvt_kernel(const int* __restrict__ ti, const int* __restrict__ mi,
                           float* __restrict__ out){
  int i = blockIdx.x*blockDim.x + threadIdx.x;
  if (i < 65536*8){
    out[65536 + i]           = (float)ti[i];
    out[65536 + 65536*8 + i] = (float)mi[i];
  }
}

// ---------------------------------------------------------------- host ----
extern "C" void kernel_launch(void* const* d_in, const int* in_sizes, int n_in,
                              void* d_out, int out_size)
{
  (void)in_sizes; (void)n_in;
  const float* z1    = (const float*)d_in[0];
  const float* z2    = (const float*)d_in[1];
  const int*   t_act = (const int*)  d_in[2];
  const int*   m_act = (const int*)  d_in[3];
  const float* aemb  = (const float*)d_in[4];
  const float* bemb  = (const float*)d_in[5];
  const float* idemb = (const float*)d_in[6];
  const float* Wih   = (const float*)d_in[7];
  const float* Whh   = (const float*)d_in[8];
  const float* bih   = (const float*)d_in[9];
  const float* bhh   = (const float*)d_in[10];
  const float* Wt    = (const float*)d_in[11];
  const float* bt    = (const float*)d_in[12];
  const float* Wm    = (const float*)d_in[13];
  const float* bm    = (const float*)d_in[14];
  float* out = (float*)d_out;

  const int SMEM_BYTES = (2*256*HSTR + 4*RPAIR*256) * (int)sizeof(ull); // 106496
  cudaFuncSetAttribute(decoder_kernel, cudaFuncAttributeMaxDynamicSharedMemorySize, SMEM_BYTES);

  prep_w4_kernel<<<256,256>>>(Wih, Whh);
  prep_kernel<<<4,256>>>(Wih,bih,bhh,aemb,bemb,idemb);
  decoder_kernel<<<BATCH/RB, NTH, SMEM_BYTES>>>(z1,z2,t_act,m_act,Wt,bt,Wm,bm,out);

  const int NACT = 65536*8;  // elements in t_actions (= m_actions)
  if (out_size >= 65536 + 2*NACT + 2){
    // tree-flatten layout: [log_p | t_actions | m_actions | t_ent | m_ent]
    cvt_kernel<<<(NACT+255)/256,256>>>(t_act, m_act, out);
    finalize_kernel<<<1,32>>>(out, 65536 + 2*NACT);
  } else if (out_size >= 65536 + 2){
    finalize_kernel<<<1,32>>>(out, 65536);
  }
  // else: log_p-only layout; main kernel already wrote out[0..B)
}